// round 5
// baseline (speedup 1.0000x reference)
#include <cuda_runtime.h>

// Problem constants (fixed by the reference)
#define SEQ_LEN   512
#define EMB       768
#define NLAB      9
#define FEAT      2354            // 3*768 + 50
#define WDIM      50
#define MAXW      16
#define NSPANS    32768
#define HALF_K    384             // EMB/2, staged per smem pass
#define ABLK      64              // K_A blocks
#define TOTAL_OUT (NSPANS * NLAB) // 294912
#define BBLK      288             // K_B blocks: 288*256*4 == TOTAL_OUT exactly

// Packed tables (allocation-free rule: __device__ globals)
// g_S[t*9+l] = (Ps[t][l], Pc[t][l])   Pc[t] = sum of Pa over tokens [0,t)
// g_E[t*9+l] = (Pe[t][l], Pc[t][l])
// g_Wb[w*9+l] = (width_proj + bias, 1/w)
__device__ float2 g_S[SEQ_LEN * NLAB];
__device__ float2 g_E[SEQ_LEN * NLAB];
__device__ float  g_Pa[SEQ_LEN * NLAB];
__device__ float2 g_Wb[(MAXW + 1) * NLAB];
__device__ unsigned g_ticket = 0;     // reset by last block each call -> replay-safe

// ---------------------------------------------------------------------------
// K_A: token projections (warp-per-token, smem-staged W) + width table
// (block 0, concurrent) + scan done by the LAST block to finish (ticket
// pattern: one atomic, no spinning).
// ---------------------------------------------------------------------------
__global__ void __launch_bounds__(256)
proj_scan_kernel(const float* __restrict__ seq,
                 const float* __restrict__ wt,
                 const float* __restrict__ W,
                 const float* __restrict__ b) {
    __shared__ __align__(16) float sw[27 * HALF_K];   // 41.5 KB
    __shared__ bool s_last;

    const int tid  = threadIdx.x;
    const int bid  = blockIdx.x;
    const int warp = tid >> 5;
    const int lane = tid & 31;
    const int tok  = bid * 8 + warp;

    float acc[27];
    #pragma unroll
    for (int j = 0; j < 27; j++) acc[j] = 0.f;

    #pragma unroll
    for (int c = 0; c < 2; c++) {
        // Stage 27 x 384-float half-chunk of W (float2: rows 8B-aligned).
        for (int i = tid; i < 27 * (HALF_K / 2); i += 256) {
            const int j = i / (HALF_K / 2);
            const int p = (i % (HALF_K / 2)) * 2;
            const int l = j % 9, sl = j / 9;
            const float2 v = __ldg(reinterpret_cast<const float2*>(
                W + (size_t)l * FEAT + sl * EMB + c * HALF_K + p));
            sw[j * HALF_K + p]     = v.x;
            sw[j * HALF_K + p + 1] = v.y;
        }
        __syncthreads();

        #pragma unroll
        for (int it = 0; it < 3; it++) {
            const int ko = it * 128 + lane * 4;
            const float4 sv = *reinterpret_cast<const float4*>(
                seq + (size_t)tok * EMB + c * HALF_K + ko);
            #pragma unroll
            for (int j = 0; j < 27; j++) {
                const float4 w4 = *reinterpret_cast<const float4*>(sw + j * HALF_K + ko);
                acc[j] += sv.x * w4.x + sv.y * w4.y + sv.z * w4.z + sv.w * w4.w;
            }
        }
        __syncthreads();
    }

    // Warp reductions; lane 0 writes the .x slots / Pa.
    #pragma unroll
    for (int j = 0; j < 27; j++) {
        #pragma unroll
        for (int o = 16; o > 0; o >>= 1)
            acc[j] += __shfl_down_sync(0xffffffffu, acc[j], o);
    }
    if (lane == 0) {
        #pragma unroll
        for (int j = 0; j < 27; j++) {
            const int l = j % 9, sl = j / 9;
            if (sl == 0)      reinterpret_cast<float*>(g_S)[(tok * NLAB + l) * 2] = acc[j];
            else if (sl == 1) reinterpret_cast<float*>(g_E)[(tok * NLAB + l) * 2] = acc[j];
            else              g_Pa[tok * NLAB + l] = acc[j];
        }
    }

    // Width table + per-width reciprocal (block 0, independent of the above).
    if (bid == 0 && tid < (MAXW + 1) * NLAB) {
        const int w = tid / NLAB;
        const int l = tid % NLAB;
        const float* wrow = W + (size_t)l * FEAT + 3 * EMB;
        float a = __ldg(b + l);
        #pragma unroll
        for (int k = 0; k < WDIM; k++)
            a += __ldg(wt + w * WDIM + k) * __ldg(wrow + k);
        g_Wb[tid] = make_float2(a, 1.0f / (float)w);   // w=0 entry never read
    }

    // ---- last-block ticket: the final arriver does the scan (no spinning) --
    __threadfence();
    __syncthreads();
    if (tid == 0)
        s_last = (atomicAdd(&g_ticket, 1) == (unsigned)(gridDim.x - 1));
    __syncthreads();
    if (!s_last) return;

    if (tid == 0) g_ticket = 0;          // reset for next graph replay
    __threadfence();                     // acquire other blocks' Pa writes

    // 256 threads, thread handles tokens (2*tid, 2*tid+1), 9 labels each.
    float* tot   = sw;                   // reuse smem: [8][9] warp pair-totals
    float* carry = sw + 8 * NLAB;        // [8][9]

    const int t0 = tid * 2;
    float a0[NLAB], a1[NLAB], pr[NLAB];
    #pragma unroll
    for (int l = 0; l < NLAB; l++) {
        a0[l] = __ldcg(&g_Pa[t0 * NLAB + l]);          // L1-bypass: cross-block
        a1[l] = __ldcg(&g_Pa[(t0 + 1) * NLAB + l]);
        pr[l] = a0[l] + a1[l];
    }
    float inc[NLAB];
    #pragma unroll
    for (int l = 0; l < NLAB; l++) {
        float x = pr[l];
        #pragma unroll
        for (int o = 1; o < 32; o <<= 1) {
            const float y = __shfl_up_sync(0xffffffffu, x, o);
            if (lane >= o) x += y;
        }
        inc[l] = x;
    }
    if (lane == 31) {
        #pragma unroll
        for (int l = 0; l < NLAB; l++) tot[warp * NLAB + l] = inc[l];
    }
    __syncthreads();
    if (tid < NLAB) {
        float r = 0.f;
        #pragma unroll
        for (int w = 0; w < 8; w++) { carry[w * NLAB + tid] = r; r += tot[w * NLAB + tid]; }
    }
    __syncthreads();
    #pragma unroll
    for (int l = 0; l < NLAB; l++) {
        const float pc0 = inc[l] - pr[l] + carry[warp * NLAB + l];  // Pc[t0]
        const float pc1 = pc0 + a0[l];                              // Pc[t0+1]
        reinterpret_cast<float*>(g_S)[(t0 * NLAB + l) * 2 + 1] = pc0;
        reinterpret_cast<float*>(g_E)[(t0 * NLAB + l) * 2 + 1] = pc0;
        reinterpret_cast<float*>(g_S)[((t0 + 1) * NLAB + l) * 2 + 1] = pc1;
        reinterpret_cast<float*>(g_E)[((t0 + 1) * NLAB + l) * 2 + 1] = pc1;
    }
}

// ---------------------------------------------------------------------------
// K_B: assemble logits. 4 elements/thread, indices batched before the
// dependent table loads (MLP on the idx->table chain). Exact-cover grid.
// ---------------------------------------------------------------------------
__global__ void __launch_bounds__(256)
assemble_kernel(const int* __restrict__ st,
                const int* __restrict__ en,
                const int* __restrict__ wd,
                float* __restrict__ out) {
    const int base   = blockIdx.x * 256 + threadIdx.x;
    const int stride = BBLK * 256;                    // 73728

    int sp[4], lb[4], s[4], e[4], w[4];
    #pragma unroll
    for (int i = 0; i < 4; i++) {
        const int m = base + i * stride;
        sp[i] = m / NLAB;
        lb[i] = m - sp[i] * NLAB;
        s[i] = __ldg(st + sp[i]);
        e[i] = __ldg(en + sp[i]);
        w[i] = __ldg(wd + sp[i]);
    }
    float2 fs[4], fe[4], fw[4];
    #pragma unroll
    for (int i = 0; i < 4; i++) {
        fs[i] = g_S[s[i] * NLAB + lb[i]];
        fe[i] = g_E[e[i] * NLAB + lb[i]];
        fw[i] = g_Wb[w[i] * NLAB + lb[i]];
    }
    #pragma unroll
    for (int i = 0; i < 4; i++)
        out[base + i * stride] = fs[i].x + fe[i].x + (fe[i].y - fs[i].y) * fw[i].y + fw[i].x;
}

// ---------------------------------------------------------------------------
extern "C" void kernel_launch(void* const* d_in, const int* in_sizes, int n_in,
                              void* d_out, int out_size) {
    const float* seq = (const float*)d_in[0];   // [1,512,768]
    const int*   st  = (const int*)  d_in[1];   // [32768]
    const int*   en  = (const int*)  d_in[2];   // [32768]
    const int*   wd  = (const int*)  d_in[3];   // [32768]
    const float* wt  = (const float*)d_in[4];   // [17,50]
    const float* W   = (const float*)d_in[5];   // [9,2354]
    const float* b   = (const float*)d_in[6];   // [9]
    float* out = (float*)d_out;                 // [32768,9]

    proj_scan_kernel<<<ABLK, 256>>>(seq, wt, W, b);
    assemble_kernel<<<BBLK, 256>>>(st, en, wd, out);
}